// round 15
// baseline (speedup 1.0000x reference)
#include <cuda_runtime.h>
#include <cstdint>

#define TT 16384
#define DD 2048
#define EE 64
#define KSEL 8
#define BR 64
#define DC 32
#define NIT (DD / DC)       // 64 stages
#define XSTR 34             // X smem row stride (floats): 8B-aligned, bank-staggered
#define WSTR 68             // W smem d-row stride (floats): 16B-aligned
#define XBUF (BR * XSTR)    // 2176 floats
#define WBUF (DC * WSTR)    // 2176 floats
// dynamic smem = 2*XBUF + 2*WBUF = 8704 floats = 34816 B  -> 2 blocks/SM
// epilogue overlay L[64][68] = 4352 floats fits inside.

typedef unsigned long long ull;

__device__ float g_wt[DD * EE];   // transposed W: g_wt[d*64 + e] = W[e][d]
__device__ float g_cnt[EE];
__device__ float g_pn[EE];
__device__ int   g_done;

// ---------------------------------------------------------------------------
// Kernel A: zero accumulators + coalesced tiled transpose of W to d-major.
// ---------------------------------------------------------------------------
__global__ void prep_kernel(const float* __restrict__ W) {
    __shared__ float tile[64][65];
    const int t = threadIdx.x;
    const int d0 = blockIdx.x * 64;

    if (blockIdx.x == 0) {
        if (t < EE)            g_cnt[t] = 0.f;
        else if (t < 2 * EE)   g_pn[t - EE] = 0.f;
        else if (t == 2 * EE)  g_done = 0;
    }

    #pragma unroll
    for (int j = 0; j < 16; j++) {
        int idx = j * 256 + t;
        int e = idx >> 6, dl = idx & 63;
        tile[e][dl] = W[(size_t)e * DD + d0 + dl];
    }
    __syncthreads();
    #pragma unroll
    for (int j = 0; j < 16; j++) {
        int idx = j * 256 + t;
        int dl = idx >> 6, e = idx & 63;
        g_wt[(size_t)(d0 + dl) * EE + e] = tile[e][dl];
    }
}

// packed fp32x2 FMA: each 32-bit lane is an independent sequential FFMA chain
__device__ __forceinline__ void ffma2(ull& c, ull a, ull b) {
    asm volatile("fma.rn.f32x2 %0, %1, %2, %0;" : "+l"(c) : "l"(a), "l"(b));
}
__device__ __forceinline__ ull dup32(uint32_t v) {
    ull r; asm("mov.b64 %0, {%1,%1};" : "=l"(r) : "r"(v)); return r;
}

extern __shared__ float smem[];

// ---------------------------------------------------------------------------
// Fused router: 256 blocks x 256 threads, 64 rows/block (R7/R14-proven body,
// halved tile for 2 blocks/SM = 4 warps/SMSP latency hiding).
// Warp wi owns experts 8wi..8wi+7 (W loads warp-uniform -> broadcast).
// Lane l owns rows {l, l+32}. Each lane is a plain sequential-d FFMA chain
// (exact selection; proven R5/R7/R14). Last-block ticket folds balance loss.
// ---------------------------------------------------------------------------
__global__ void __launch_bounds__(256, 2) router_kernel(
    const float* __restrict__ x,
    const float* __restrict__ bias,
    float* __restrict__ out)
{
    float* Xs  = smem;                 // [2][XBUF]
    float* Wsm = smem + 2 * XBUF;      // [2][WBUF]
    float* L   = smem;                 // epilogue overlay [64][68]

    __shared__ float bias_s[EE];
    __shared__ float cnt_s[EE];

    const int t    = threadIdx.x;
    const int wi   = t >> 5;
    const int lane = t & 31;
    const int r0   = blockIdx.x * BR;

    if (t < EE) { bias_s[t] = bias[t]; cnt_s[t] = 0.f; }

    // ---- X staging via 8B cp.async: thread t -> row t>>2, 8 floats (t&3)
    const int xrow = t >> 2;
    const int xq   = t & 3;
    const float* xsrc = x + (size_t)(r0 + xrow) * DD + xq * 8;
    const uint32_t xdst = (uint32_t)__cvta_generic_to_shared(
        Xs + xrow * XSTR + xq * 8);
    const uint32_t XBUF_B = XBUF * 4;

    // ---- W staging via 16B cp.async: 512 chunks/stage, 2 per thread
    const int d1 = t >> 4,        q1 = t & 15;
    const int d2 = (t + 256) >> 4;  // q same
    const float* wsrc1 = g_wt + (size_t)d1 * EE + 4 * q1;
    const float* wsrc2 = g_wt + (size_t)d2 * EE + 4 * q1;
    const uint32_t wdst1 = (uint32_t)__cvta_generic_to_shared(
        Wsm + d1 * WSTR + 4 * q1);
    const uint32_t wdst2 = (uint32_t)__cvta_generic_to_shared(
        Wsm + d2 * WSTR + 4 * q1);
    const uint32_t WBUF_B = WBUF * 4;

    ull acc[2][4];
    #pragma unroll
    for (int i = 0; i < 2; i++)
        #pragma unroll
        for (int p = 0; p < 4; p++) acc[i][p] = 0ULL;

    // ---- prologue: stage 0
    {
        #pragma unroll
        for (int k = 0; k < 4; k++)
            asm volatile("cp.async.ca.shared.global [%0], [%1], 8;"
                         :: "r"(xdst + 8 * k), "l"(xsrc + 2 * k));
        asm volatile("cp.async.cg.shared.global [%0], [%1], 16;" :: "r"(wdst1), "l"(wsrc1));
        asm volatile("cp.async.cg.shared.global [%0], [%1], 16;" :: "r"(wdst2), "l"(wsrc2));
        asm volatile("cp.async.commit_group;");
    }

    for (int s = 0; s < NIT; s++) {
        const int b = s & 1;

        if (s + 1 < NIT) {
            // prefetch stage s+1 into the other buffer
            const uint32_t xo = (b ^ 1) ? XBUF_B : 0u;
            const uint32_t wo = (b ^ 1) ? WBUF_B : 0u;
            const float* xs = xsrc + (size_t)(s + 1) * DC;
            const float* w1 = wsrc1 + (size_t)(s + 1) * DC * EE;
            const float* w2 = wsrc2 + (size_t)(s + 1) * DC * EE;
            #pragma unroll
            for (int k = 0; k < 4; k++)
                asm volatile("cp.async.ca.shared.global [%0], [%1], 8;"
                             :: "r"(xdst + xo + 8 * k), "l"(xs + 2 * k));
            asm volatile("cp.async.cg.shared.global [%0], [%1], 16;" :: "r"(wdst1 + wo), "l"(w1));
            asm volatile("cp.async.cg.shared.global [%0], [%1], 16;" :: "r"(wdst2 + wo), "l"(w2));
            asm volatile("cp.async.commit_group;");
            asm volatile("cp.async.wait_group 1;");
        } else {
            asm volatile("cp.async.wait_group 0;");
        }
        __syncthreads();

        // ---- compute stage s
        const float* xb = Xs + b * XBUF + lane * XSTR;
        const float* wb = Wsm + b * WBUF + 8 * wi;
        #pragma unroll 8
        for (int dl = 0; dl < DC; dl += 2) {
            ulonglong2 wa0 = *(const ulonglong2*)(wb + dl * WSTR);
            ulonglong2 wa1 = *(const ulonglong2*)(wb + dl * WSTR + 4);
            ulonglong2 wb0 = *(const ulonglong2*)(wb + (dl + 1) * WSTR);
            ulonglong2 wb1 = *(const ulonglong2*)(wb + (dl + 1) * WSTR + 4);
            #pragma unroll
            for (int i = 0; i < 2; i++) {
                uint2 xv = *(const uint2*)(xb + i * (32 * XSTR) + dl);
                ull xa = dup32(xv.x);     // (x_d, x_d)
                ull xc = dup32(xv.y);     // (x_{d+1}, x_{d+1})
                ffma2(acc[i][0], xa, wa0.x);
                ffma2(acc[i][1], xa, wa0.y);
                ffma2(acc[i][2], xa, wa1.x);
                ffma2(acc[i][3], xa, wa1.y);
                ffma2(acc[i][0], xc, wb0.x);
                ffma2(acc[i][1], xc, wb0.y);
                ffma2(acc[i][2], xc, wb1.x);
                ffma2(acc[i][3], xc, wb1.y);
            }
        }
        __syncthreads();   // buffer b free before iter s+2 refills it
    }

    // ---- logits -> L[64][68]
    #pragma unroll
    for (int i = 0; i < 2; i++) {
        #pragma unroll
        for (int p = 0; p < 4; p++) {
            float2 f = *(float2*)&acc[i][p];
            const int rr = lane + 32 * i;
            const int ee = 8 * wi + 2 * p;
            L[rr * 68 + ee]     = f.x;
            L[rr * 68 + ee + 1] = f.y;
        }
    }
    __syncthreads();

    // ---- per-row: sigmoid, stable top-8 (strict > = lowest-index ties), gates
    if (t < BR) {
        float* Lr = L + t * 68;

        float ssum = 0.f;
        #pragma unroll
        for (int e = 0; e < EE; e++) {
            float sg = 1.f / (1.f + expf(-Lr[e]));
            Lr[e] = sg;
            ssum += sg;
        }

        ull mask = 0ULL;
        float gsum = 0.f;
        float gv[KSEL];
        int   gi[KSEL];
        #pragma unroll
        for (int k = 0; k < KSEL; k++) {
            float best = -3.4e38f;
            int bi = 0;
            for (int e = 0; e < EE; e++) {
                if ((mask >> e) & 1ULL) continue;
                float v = Lr[e] + bias_s[e];
                if (v > best) { best = v; bi = e; }
            }
            mask |= (1ULL << bi);
            gi[k] = bi;
            float a = Lr[bi];
            gv[k] = a;
            gsum += a;
            atomicAdd(&cnt_s[bi], 1.f);
        }

        const float inv = 1.f / (gsum + 1e-9f);
        const size_t rgl = (size_t)r0 + t;
        #pragma unroll
        for (int k = 0; k < KSEL; k++) {
            out[rgl * KSEL + k]                     = gv[k] * inv;
            out[(size_t)TT * KSEL + rgl * KSEL + k] = (float)gi[k];
        }

        const float pinv = 1.f / (ssum + 1e-9f);
        #pragma unroll
        for (int e = 0; e < EE; e++) Lr[e] *= pinv;   // affinity_norm for P
    }
    __syncthreads();

    // ---- per-expert partial sums of affinity_norm -> global atomics
    {
        const int e   = t & 63;
        const int seg = t >> 6;        // 4 segments x 16 rows
        float s = 0.f;
        #pragma unroll
        for (int r = seg * 16; r < seg * 16 + 16; r++) s += L[r * 68 + e];
        atomicAdd(&g_pn[e], s);
    }
    if (t < EE) atomicAdd(&g_cnt[t], cnt_s[t]);
    __syncthreads();

    // ---- last-block ticket: fold the balance loss
    if (t == 0) {
        __threadfence();
        if (atomicAdd(&g_done, 1) == gridDim.x - 1) {
            float s = 0.f;
            for (int i = 0; i < EE; i++) {
                float c = atomicAdd(&g_cnt[i], 0.f);   // L2-coherent read
                float p = atomicAdd(&g_pn[i], 0.f);
                s += c * p;
            }
            double loss = (double)s * 1e-4 * 64.0 / (8.0 * 16384.0) / 16384.0;
            out[(size_t)2 * TT * KSEL] = (float)loss;
        }
    }
}

// ---------------------------------------------------------------------------
extern "C" void kernel_launch(void* const* d_in, const int* in_sizes, int n_in,
                              void* d_out, int out_size) {
    const float* x    = (const float*)d_in[0];
    const float* W    = (const float*)d_in[1];
    const float* bias = (const float*)d_in[2];
    float* out = (float*)d_out;

    prep_kernel<<<32, 256>>>(W);
    router_kernel<<<TT / BR, 256, 34816>>>(x, bias, out);
}